// round 2
// baseline (speedup 1.0000x reference)
#include <cuda_runtime.h>
#include <math.h>

#define B_TOTAL 65536
#define KDIM 512

// Ping-pong activation buffers (allocation-free scratch).
__device__ float g_bufA[(size_t)B_TOTAL * KDIM];
__device__ float g_bufB[(size_t)B_TOTAL * KDIM];

__device__ __forceinline__ float act_clip(float h, int f, float mx) {
    float o;
    if (f == 0) {
        o = fmaxf(h, 0.0f);                       // ReLU
    } else if (f == 1) {
        o = 1.0f / (1.0f + __expf(-h));           // Sigmoid
    } else if (f == 2) {
        o = tanhf(h);                             // Tanh
    } else if (f == 3) {
        o = (h > 0.0f) ? h : 0.1f * h;            // LeakyReLU(0.1)
    } else {
        const float sc = 1.0507009873554805f;     // SELU
        const float al = 1.6732632423543772f;
        o = (h > 0.0f) ? sc * h : sc * al * (__expf(h) - 1.0f);
    }
    return fminf(o, mx);
}

// C[M, N] = act_clip(A[M, K] @ W[N, K]^T + bias)   (K = 512 fixed)
// Block tile 128x128, BK=8, 256 threads, 8x8 per-thread microtile,
// double-buffered shared memory.
__global__ void __launch_bounds__(256)
fused_layer(const float* __restrict__ A,
            const float* __restrict__ W,
            const float* __restrict__ bias,
            const int*   __restrict__ fid,
            const float* __restrict__ mx,
            float* __restrict__ C,
            int N)
{
    constexpr int BM = 128, BK = 8, K = KDIM;
    __shared__ float As[2][BK][BM];
    __shared__ float Bs[2][BK][BM];

    const int bm  = blockIdx.x * BM;
    const int bn  = blockIdx.y * BM;
    const int tid = threadIdx.x;
    const int tx  = tid & 15;       // n-dim thread coord (0..15)
    const int ty  = tid >> 4;       // m-dim thread coord (0..15)

    // global->smem staging: each thread loads one float4 of A tile and W tile
    const int lrow = tid >> 1;           // 0..127
    const int lk   = (tid & 1) * 4;      // 0 or 4

    const float* Ap = A + (size_t)(bm + lrow) * K + lk;
    const float* Wp = W + (size_t)(bn + lrow) * K + lk;

    float acc[8][8];
    #pragma unroll
    for (int i = 0; i < 8; ++i)
        #pragma unroll
        for (int j = 0; j < 8; ++j) acc[i][j] = 0.0f;

    // prologue: stage k-tile 0
    float4 a4 = *(const float4*)Ap;
    float4 b4 = *(const float4*)Wp;
    As[0][lk+0][lrow] = a4.x; As[0][lk+1][lrow] = a4.y;
    As[0][lk+2][lrow] = a4.z; As[0][lk+3][lrow] = a4.w;
    Bs[0][lk+0][lrow] = b4.x; Bs[0][lk+1][lrow] = b4.y;
    Bs[0][lk+2][lrow] = b4.z; Bs[0][lk+3][lrow] = b4.w;
    __syncthreads();

    int buf = 0;
    constexpr int NT = K / BK;  // 64 k-tiles
    for (int kt = 0; kt < NT; ++kt) {
        if (kt + 1 < NT) {
            a4 = *(const float4*)(Ap + (kt + 1) * BK);
            b4 = *(const float4*)(Wp + (kt + 1) * BK);
        }
        #pragma unroll
        for (int k = 0; k < BK; ++k) {
            float4 ar0 = *(const float4*)&As[buf][k][ty * 8];
            float4 ar1 = *(const float4*)&As[buf][k][ty * 8 + 4];
            float4 br0 = *(const float4*)&Bs[buf][k][tx * 8];
            float4 br1 = *(const float4*)&Bs[buf][k][tx * 8 + 4];
            float ar[8] = {ar0.x, ar0.y, ar0.z, ar0.w, ar1.x, ar1.y, ar1.z, ar1.w};
            float br[8] = {br0.x, br0.y, br0.z, br0.w, br1.x, br1.y, br1.z, br1.w};
            #pragma unroll
            for (int i = 0; i < 8; ++i)
                #pragma unroll
                for (int j = 0; j < 8; ++j)
                    acc[i][j] = fmaf(ar[i], br[j], acc[i][j]);
        }
        if (kt + 1 < NT) {
            const int nb = buf ^ 1;
            As[nb][lk+0][lrow] = a4.x; As[nb][lk+1][lrow] = a4.y;
            As[nb][lk+2][lrow] = a4.z; As[nb][lk+3][lrow] = a4.w;
            Bs[nb][lk+0][lrow] = b4.x; Bs[nb][lk+1][lrow] = b4.y;
            Bs[nb][lk+2][lrow] = b4.z; Bs[nb][lk+3][lrow] = b4.w;
            __syncthreads();
            buf = nb;
        }
    }

    // epilogue: bias + per-column activation + clip, vectorized stores
    const int col0 = bn + tx * 8;
    float bv[8], mv[8];
    int   fv[8];
    #pragma unroll
    for (int j = 0; j < 8; ++j) {
        bv[j] = __ldg(bias + col0 + j);
        fv[j] = __ldg(fid  + col0 + j);
        mv[j] = __ldg(mx   + col0 + j);
    }
    #pragma unroll
    for (int i = 0; i < 8; ++i) {
        const int row = bm + ty * 8 + i;
        float v[8];
        #pragma unroll
        for (int j = 0; j < 8; ++j)
            v[j] = act_clip(acc[i][j] + bv[j], fv[j], mv[j]);
        *(float4*)(C + (size_t)row * N + col0)     = make_float4(v[0], v[1], v[2], v[3]);
        *(float4*)(C + (size_t)row * N + col0 + 4) = make_float4(v[4], v[5], v[6], v[7]);
    }
}

extern "C" void kernel_launch(void* const* d_in, const int* in_sizes, int n_in,
                              void* d_out, int out_size) {
    const float* x      = (const float*)d_in[0];   // [65536, 512]
    const float* W_in   = (const float*)d_in[1];   // [512, 512]
    const float* b_in   = (const float*)d_in[2];   // [512]
    const float* W_h    = (const float*)d_in[3];   // [4, 512, 512]
    const float* b_h    = (const float*)d_in[4];   // [4, 512]
    const float* W_out  = (const float*)d_in[5];   // [128, 512]
    const float* b_out  = (const float*)d_in[6];   // [128]
    const float* m_in   = (const float*)d_in[7];   // [512]
    const float* m_h    = (const float*)d_in[8];   // [4, 512]
    const float* m_out  = (const float*)d_in[9];   // [128]
    const int*   fid_in = (const int*)d_in[10];    // [512]
    const int*   fid_h  = (const int*)d_in[11];    // [4, 512]
    const int*   fid_out= (const int*)d_in[12];    // [128]
    float* out = (float*)d_out;                    // [65536, 128]

    float* bufA;
    float* bufB;
    cudaGetSymbolAddress((void**)&bufA, g_bufA);
    cudaGetSymbolAddress((void**)&bufB, g_bufB);

    dim3 blk(256);
    dim3 g512(B_TOTAL / 128, 512 / 128);
    dim3 g128(B_TOTAL / 128, 128 / 128);

    // input layer
    fused_layer<<<g512, blk>>>(x, W_in, b_in, fid_in, m_in, bufA, 512);

    // 4 hidden layers, ping-pong
    const float* cur = bufA;
    float* nxt = bufB;
    for (int i = 0; i < 4; ++i) {
        fused_layer<<<g512, blk>>>(cur,
                                   W_h + (size_t)i * 512 * 512,
                                   b_h + i * 512,
                                   fid_h + i * 512,
                                   m_h + i * 512,
                                   nxt, 512);
        float* t = nxt;
        nxt = (float*)cur;
        cur = t;
    }

    // output layer
    fused_layer<<<g128, blk>>>(cur, W_out, b_out, fid_out, m_out, out, 128);
}